// round 4
// baseline (speedup 1.0000x reference)
#include <cuda_runtime.h>
#include <cuda_bf16.h>
#include <cstdint>

#define DIM 1024
#define HEADS 16
#define DHEAD 64
#define BATCH 2
#define SEQ 2048
#define TOKENS (BATCH*SEQ)   // 4096
#define QKV_N (3*DIM)        // 3072

// ---------------- scratch -----------------------------------------------------
__device__ float g_xn[TOKENS*DIM];
__device__ __nv_bfloat16 g_xn_hi[TOKENS*DIM];
__device__ __nv_bfloat16 g_xn_lo[TOKENS*DIM];
__device__ __nv_bfloat16 g_wqkvT_hi[QKV_N*DIM];   // [n][k]
__device__ __nv_bfloat16 g_wqkvT_lo[QKV_N*DIM];
__device__ __nv_bfloat16 g_woutT_hi[DIM*DIM];
__device__ __nv_bfloat16 g_woutT_lo[DIM*DIM];
__device__ float g_q[BATCH*HEADS*SEQ*DHEAD];
__device__ float g_k[BATCH*HEADS*SEQ*DHEAD];
__device__ float g_v[BATCH*HEADS*SEQ*DHEAD];
__device__ float g_gates[TOKENS*HEADS];
__device__ __nv_bfloat16 g_m_hi[TOKENS*DIM];
__device__ __nv_bfloat16 g_m_lo[TOKENS*DIM];
__device__ float g_rope[SEQ*DHEAD];

// ---------------- mma.sync helpers (base sm_80+ features, compute_103-safe) ---
__device__ __forceinline__ uint32_t smem_u32(const void* p) {
    uint32_t a;
    asm("{ .reg .u64 t; cvta.to.shared.u64 t, %1; cvt.u32.u64 %0, t; }" : "=r"(a) : "l"(p));
    return a;
}
__device__ __forceinline__ void ldm_x4(uint32_t* r, uint32_t addr) {
    asm volatile("ldmatrix.sync.aligned.m8n8.x4.shared.b16 {%0,%1,%2,%3}, [%4];"
        : "=r"(r[0]), "=r"(r[1]), "=r"(r[2]), "=r"(r[3]) : "r"(addr));
}
__device__ __forceinline__ void mma16816(float* d, const uint32_t* a, uint32_t b0, uint32_t b1) {
    asm volatile("mma.sync.aligned.m16n8k16.row.col.f32.bf16.bf16.f32 "
        "{%0,%1,%2,%3}, {%4,%5,%6,%7}, {%8,%9}, {%0,%1,%2,%3};"
        : "+f"(d[0]), "+f"(d[1]), "+f"(d[2]), "+f"(d[3])
        : "r"(a[0]), "r"(a[1]), "r"(a[2]), "r"(a[3]), "r"(b0), "r"(b1));
}

// ---------------- RoPE table --------------------------------------------------
__global__ void rope_table_kernel(const float* __restrict__ freqs) {
    int idx = blockIdx.x * blockDim.x + threadIdx.x;
    if (idx >= SEQ * 32) return;
    int pos = idx >> 5, p = idx & 31;
    float f = (float)pos * freqs[p];
    g_rope[pos*64 + p*2 + 0] = cosf(f);
    g_rope[pos*64 + p*2 + 1] = sinf(f);
}

// ---------------- RMSNorm + bf16 split ----------------------------------------
__global__ __launch_bounds__(256) void rmsnorm_kernel(const float* __restrict__ x,
                                                      const float* __restrict__ gamma) {
    int t = blockIdx.x;
    int tid = threadIdx.x;
    const float4* xr = (const float4*)(x + (size_t)t * DIM);
    float4 v = xr[tid];
    float ss = v.x*v.x + v.y*v.y + v.z*v.z + v.w*v.w;
    __shared__ float red[8];
    #pragma unroll
    for (int o = 16; o; o >>= 1) ss += __shfl_down_sync(0xffffffffu, ss, o);
    if ((tid & 31) == 0) red[tid >> 5] = ss;
    __syncthreads();
    __shared__ float bscale;
    if (tid == 0) {
        float s = 0.f;
        #pragma unroll
        for (int i = 0; i < 8; i++) s += red[i];
        bscale = 32.0f * rsqrtf(s);
    }
    __syncthreads();
    float sc = bscale;
    float4 g = ((const float4*)gamma)[tid];
    float4 o;
    o.x = v.x * sc * g.x; o.y = v.y * sc * g.y;
    o.z = v.z * sc * g.z; o.w = v.w * sc * g.w;
    ((float4*)(g_xn + (size_t)t * DIM))[tid] = o;
    size_t e = (size_t)t * DIM + tid * 4;
    float vals[4] = {o.x, o.y, o.z, o.w};
    #pragma unroll
    for (int i = 0; i < 4; i++) {
        __nv_bfloat16 h = __float2bfloat16(vals[i]);
        g_xn_hi[e + i] = h;
        g_xn_lo[e + i] = __float2bfloat16(vals[i] - __bfloat162float(h));
    }
}

// ---------------- gates -------------------------------------------------------
__global__ __launch_bounds__(512) void gates_kernel(const float* __restrict__ wg,
                                                    const float* __restrict__ bg) {
    int t = blockIdx.x;
    int h = threadIdx.x >> 5;
    int lane = threadIdx.x & 31;
    const float* xr = g_xn + (size_t)t * DIM;
    float s = 0.f;
    #pragma unroll 8
    for (int k = lane; k < DIM; k += 32)
        s += xr[k] * wg[k * HEADS + h];
    #pragma unroll
    for (int o = 16; o; o >>= 1) s += __shfl_down_sync(0xffffffffu, s, o);
    if (lane == 0) {
        float z = s + bg[h];
        g_gates[t * HEADS + h] = 1.f / (1.f + __expf(-z));
    }
}

// ---------------- weight transpose + split ------------------------------------
__global__ __launch_bounds__(256) void transpose_split_kernel(const float* __restrict__ in,
                                                              __nv_bfloat16* __restrict__ hi,
                                                              __nv_bfloat16* __restrict__ lo,
                                                              int N) {
    __shared__ float tile[32][33];
    int n0 = blockIdx.x * 32, k0 = blockIdx.y * 32;
    #pragma unroll
    for (int r = 0; r < 4; r++)
        tile[threadIdx.y + r*8][threadIdx.x] =
            in[(size_t)(k0 + threadIdx.y + r*8) * N + n0 + threadIdx.x];
    __syncthreads();
    #pragma unroll
    for (int r = 0; r < 4; r++) {
        int n = n0 + threadIdx.y + r*8;
        int k = k0 + threadIdx.x;
        float v = tile[threadIdx.x][threadIdx.y + r*8];
        __nv_bfloat16 h = __float2bfloat16(v);
        hi[(size_t)n * DIM + k] = h;
        lo[(size_t)n * DIM + k] = __float2bfloat16(v - __bfloat162float(h));
    }
}

// ---------------- split-bf16 GEMM via mma.sync --------------------------------
// C[4096, N] = (Ahi+Alo)[4096,1024] @ (Bhi+Blo)^T, B stored [N][1024].
// CTA 128x128, 8 warps (4 M x 2 N), warp tile 32x64, K chunk 64.
// Smem rows padded to 72 bf16 (144B) for conflict-free ldmatrix.
#define SROW 144
#define TILE_BYTES (128*SROW)      // 18432
#define GEMM_SMEM (4*TILE_BYTES)   // 73728

__device__ __forceinline__ void qkv_store(int t, int c, float v0, float v1) {
    int s = c >> 10, rem = c & 1023, h = rem >> 6, dd = rem & 63;  // dd even
    int b = t >> 11, pos = t & (SEQ - 1);
    float* dst = ((s == 0) ? g_q : (s == 1) ? g_k : g_v)
                 + ((size_t)(b * HEADS + h) * SEQ + pos) * DHEAD + dd;
    if (s < 2) {
        float cw = g_rope[pos*64 + dd], sw = g_rope[pos*64 + dd + 1];
        float2 o;
        o.x = v0 * cw - v1 * sw;
        o.y = v1 * cw + v0 * sw;
        *(float2*)dst = o;
    } else {
        float2 o; o.x = v0; o.y = v1;
        *(float2*)dst = o;
    }
}

template<int MODE>
__global__ __launch_bounds__(256) void mma_gemm_kernel(const __nv_bfloat16* __restrict__ Bhi_g,
                                                       const __nv_bfloat16* __restrict__ Blo_g,
                                                       float* __restrict__ C) {
    extern __shared__ char sm[];
    char* sAh = sm;
    char* sAl = sm + TILE_BYTES;
    char* sBh = sm + 2*TILE_BYTES;
    char* sBl = sm + 3*TILE_BYTES;
    uint32_t uAh = smem_u32(sAh), uAl = smem_u32(sAl);
    uint32_t uBh = smem_u32(sBh), uBl = smem_u32(sBl);

    const __nv_bfloat16* Ahi = (MODE == 0) ? g_xn_hi : g_m_hi;
    const __nv_bfloat16* Alo = (MODE == 0) ? g_xn_lo : g_m_lo;

    int tid = threadIdx.x;
    int wid = tid >> 5, lane = tid & 31;
    int wm = wid & 3, wn = wid >> 2;
    int m0 = blockIdx.y * 128, n0 = blockIdx.x * 128;

    float acc[2][8][4];
    #pragma unroll
    for (int i = 0; i < 2; i++)
        #pragma unroll
        for (int j = 0; j < 8; j++)
            #pragma unroll
            for (int r = 0; r < 4; r++) acc[i][j][r] = 0.f;

    for (int k0 = 0; k0 < DIM; k0 += 64) {
        #pragma unroll
        for (int p = 0; p < 4; p++) {
            int u = tid + p * 256;           // 0..1023 16B-units
            int row = u >> 3;
            int cb = (u & 7) * 16;
            size_t ga = ((size_t)(m0 + row) * DIM + k0) * 2 + cb;
            size_t gb = ((size_t)(n0 + row) * DIM + k0) * 2 + cb;
            int so = row * SROW + cb;
            *(uint4*)(sAh + so) = *(const uint4*)((const char*)Ahi + ga);
            *(uint4*)(sAl + so) = *(const uint4*)((const char*)Alo + ga);
            *(uint4*)(sBh + so) = *(const uint4*)((const char*)Bhi_g + gb);
            *(uint4*)(sBl + so) = *(const uint4*)((const char*)Blo_g + gb);
        }
        __syncthreads();

        #pragma unroll
        for (int ks = 0; ks < 4; ks++) {
            int kb = ks * 32;                 // byte offset of k-step (16 bf16)
            int lrow = lane & 15;
            int lcol = (lane >> 4) * 16;      // 8 bf16 = 16B half
            uint32_t Ah[2][4], Al[2][4], Bh[4][4], Bl[4][4];
            #pragma unroll
            for (int mi = 0; mi < 2; mi++) {
                uint32_t off = (uint32_t)((wm*32 + mi*16 + lrow) * SROW + kb + lcol);
                ldm_x4(Ah[mi], uAh + off);
                ldm_x4(Al[mi], uAl + off);
            }
            #pragma unroll
            for (int nb = 0; nb < 4; nb++) {
                uint32_t off = (uint32_t)((wn*64 + nb*16 + lrow) * SROW + kb + lcol);
                ldm_x4(Bh[nb], uBh + off);
                ldm_x4(Bl[nb], uBl + off);
            }
            #pragma unroll
            for (int mi = 0; mi < 2; mi++)
                #pragma unroll
                for (int ni = 0; ni < 8; ni++) {
                    int nb = ni >> 1, half = ni & 1;
                    mma16816(acc[mi][ni], Ah[mi], Bh[nb][half], Bh[nb][2 + half]);
                    mma16816(acc[mi][ni], Ah[mi], Bl[nb][half], Bl[nb][2 + half]);
                    mma16816(acc[mi][ni], Al[mi], Bh[nb][half], Bh[nb][2 + half]);
                }
        }
        __syncthreads();
    }

    // epilogue
    #pragma unroll
    for (int mi = 0; mi < 2; mi++) {
        int r0 = m0 + wm*32 + mi*16 + (lane >> 2);
        #pragma unroll
        for (int ni = 0; ni < 8; ni++) {
            int c = n0 + wn*64 + ni*8 + (lane & 3)*2;
            if (MODE == 1) {
                float2 o0; o0.x = acc[mi][ni][0]; o0.y = acc[mi][ni][1];
                float2 o1; o1.x = acc[mi][ni][2]; o1.y = acc[mi][ni][3];
                *(float2*)(C + (size_t)r0 * DIM + c) = o0;
                *(float2*)(C + (size_t)(r0+8) * DIM + c) = o1;
            } else {
                qkv_store(r0,     c, acc[mi][ni][0], acc[mi][ni][1]);
                qkv_store(r0 + 8, c, acc[mi][ni][2], acc[mi][ni][3]);
            }
        }
    }
}

// ---------------- flash attention (smem score staging) ------------------------
__global__ __launch_bounds__(128) void attn_kernel() {
    __shared__ float4 Ks[32 * 16];
    __shared__ float4 Vs[32 * 16];
    __shared__ float  Ss[32 * 128];
    int bh = blockIdx.y;
    int b = bh >> 4, h = bh & 15;
    int qrow = blockIdx.x * 128 + threadIdx.x;
    int tid = threadIdx.x;

    const float4* qp = (const float4*)(g_q + ((size_t)bh * SEQ + qrow) * DHEAD);
    float4 q[16];
    #pragma unroll
    for (int i = 0; i < 16; i++) q[i] = qp[i];

    float4 acc[16];
    #pragma unroll
    for (int i = 0; i < 16; i++) acc[i] = make_float4(0.f, 0.f, 0.f, 0.f);
    float m = -1e30f, l = 0.f;

    for (int kt = 0; kt < SEQ; kt += 32) {
        const float4* kb = (const float4*)(g_k + ((size_t)bh * SEQ + kt) * DHEAD);
        const float4* vb = (const float4*)(g_v + ((size_t)bh * SEQ + kt) * DHEAD);
        #pragma unroll
        for (int i = 0; i < 4; i++) {
            Ks[tid + i * 128] = kb[tid + i * 128];
            Vs[tid + i * 128] = vb[tid + i * 128];
        }
        __syncthreads();

        float tmax = -1e30f;
        #pragma unroll 4
        for (int j = 0; j < 32; j++) {
            const float4* kr = &Ks[j * 16];
            float s = 0.f;
            #pragma unroll
            for (int d = 0; d < 16; d++) {
                float4 kv = kr[d];
                s += q[d].x*kv.x + q[d].y*kv.y + q[d].z*kv.z + q[d].w*kv.w;
            }
            s *= 0.125f;
            Ss[j * 128 + tid] = s;
            tmax = fmaxf(tmax, s);
        }

        float mn = fmaxf(m, tmax);
        float corr = __expf(m - mn);
        m = mn;
        l *= corr;
        #pragma unroll
        for (int d = 0; d < 16; d++) {
            acc[d].x *= corr; acc[d].y *= corr;
            acc[d].z *= corr; acc[d].w *= corr;
        }

        #pragma unroll 4
        for (int j = 0; j < 32; j++) {
            float p = __expf(Ss[j * 128 + tid] - m);
            l += p;
            const float4* vr = &Vs[j * 16];
            #pragma unroll
            for (int d = 0; d < 16; d++) {
                float4 vv = vr[d];
                acc[d].x = fmaf(p, vv.x, acc[d].x);
                acc[d].y = fmaf(p, vv.y, acc[d].y);
                acc[d].z = fmaf(p, vv.z, acc[d].z);
                acc[d].w = fmaf(p, vv.w, acc[d].w);
            }
        }
        __syncthreads();
    }

    int t = b * SEQ + qrow;
    float gate = g_gates[t * HEADS + h];
    float inv = gate / l;
    size_t mo = (size_t)t * DIM + h * DHEAD;
    #pragma unroll
    for (int d = 0; d < 16; d++) {
        float vals[4] = {acc[d].x * inv, acc[d].y * inv, acc[d].z * inv, acc[d].w * inv};
        #pragma unroll
        for (int i = 0; i < 4; i++) {
            __nv_bfloat16 hh = __float2bfloat16(vals[i]);
            g_m_hi[mo + d*4 + i] = hh;
            g_m_lo[mo + d*4 + i] = __float2bfloat16(vals[i] - __bfloat162float(hh));
        }
    }
}

// ---------------- launch ------------------------------------------------------
extern "C" void kernel_launch(void* const* d_in, const int* in_sizes, int n_in,
                              void* d_out, int out_size) {
    const float* x       = (const float*)d_in[0];
    const float* gamma   = (const float*)d_in[1];
    const float* w_qkv   = (const float*)d_in[2];
    const float* w_gates = (const float*)d_in[3];
    const float* b_gates = (const float*)d_in[4];
    const float* w_out   = (const float*)d_in[5];
    const float* freqs   = (const float*)d_in[6];
    float* out = (float*)d_out;

    cudaFuncSetAttribute(mma_gemm_kernel<0>, cudaFuncAttributeMaxDynamicSharedMemorySize, GEMM_SMEM);
    cudaFuncSetAttribute(mma_gemm_kernel<1>, cudaFuncAttributeMaxDynamicSharedMemorySize, GEMM_SMEM);

    rope_table_kernel<<<(SEQ * 32 + 255) / 256, 256>>>(freqs);
    rmsnorm_kernel<<<TOKENS, 256>>>(x, gamma);
    gates_kernel<<<TOKENS, 512>>>(w_gates, b_gates);
    transpose_split_kernel<<<dim3(QKV_N / 32, DIM / 32), dim3(32, 8)>>>(w_qkv, g_wqkvT_hi, g_wqkvT_lo, QKV_N);
    transpose_split_kernel<<<dim3(DIM / 32, DIM / 32), dim3(32, 8)>>>(w_out, g_woutT_hi, g_woutT_lo, DIM);
    {
        dim3 grid(QKV_N / 128, TOKENS / 128);
        mma_gemm_kernel<0><<<grid, 256, GEMM_SMEM>>>(g_wqkvT_hi, g_wqkvT_lo, nullptr);
    }
    {
        dim3 grid(SEQ / 128, BATCH * HEADS);
        attn_kernel<<<grid, 128>>>();
    }
    {
        dim3 grid(DIM / 128, TOKENS / 128);
        mma_gemm_kernel<1><<<grid, 256, GEMM_SMEM>>>(g_woutT_hi, g_woutT_lo, out);
    }
}

// round 5
// speedup vs baseline: 2.2392x; 2.2392x over previous
#include <cuda_runtime.h>
#include <cstdint>

#define DIM 1024
#define HEADS 16
#define DHEAD 64
#define BATCH 2
#define SEQ 2048
#define TOKENS (BATCH*SEQ)   // 4096
#define QKV_N (3*DIM)        // 3072

typedef unsigned long long u64;

// ---------------- packed f32x2 helpers (Blackwell base feature) ---------------
#define FMA2(d, a, b) asm("fma.rn.f32x2 %0, %1, %2, %0;" : "+l"(d) : "l"(a), "l"(b))
#define MUL2(d, a, b) asm("mul.rn.f32x2 %0, %1, %2;" : "=l"(d) : "l"(a), "l"(b))
__device__ __forceinline__ u64 pack2(float x) {
    u64 d; uint32_t u = __float_as_uint(x);
    asm("mov.b64 %0, {%1, %1};" : "=l"(d) : "r"(u));
    return d;
}
__device__ __forceinline__ void unpack2(u64 v, float& lo, float& hi) {
    uint32_t a, b;
    asm("mov.b64 {%0, %1}, %2;" : "=r"(a), "=r"(b) : "l"(v));
    lo = __uint_as_float(a); hi = __uint_as_float(b);
}

// ---------------- scratch -----------------------------------------------------
__device__ float g_xn[TOKENS*DIM];
__device__ float g_q[BATCH*HEADS*SEQ*DHEAD];
__device__ float g_k[BATCH*HEADS*SEQ*DHEAD];
__device__ float g_v[BATCH*HEADS*SEQ*DHEAD];
__device__ float g_gates[TOKENS*HEADS];
__device__ float g_merged[TOKENS*DIM];
__device__ float g_rope[SEQ*DHEAD];

// ---------------- RoPE table --------------------------------------------------
__global__ void rope_table_kernel(const float* __restrict__ freqs) {
    int idx = blockIdx.x * blockDim.x + threadIdx.x;
    if (idx >= SEQ * 32) return;
    int pos = idx >> 5, p = idx & 31;
    float f = (float)pos * freqs[p];
    g_rope[pos*64 + p*2 + 0] = cosf(f);
    g_rope[pos*64 + p*2 + 1] = sinf(f);
}

// ---------------- RMSNorm (L2-norm variant) -----------------------------------
__global__ __launch_bounds__(256) void rmsnorm_kernel(const float* __restrict__ x,
                                                      const float* __restrict__ gamma) {
    int t = blockIdx.x;
    int tid = threadIdx.x;
    const float4* xr = (const float4*)(x + (size_t)t * DIM);
    float4 v = xr[tid];
    float ss = v.x*v.x + v.y*v.y + v.z*v.z + v.w*v.w;
    __shared__ float red[8];
    #pragma unroll
    for (int o = 16; o; o >>= 1) ss += __shfl_down_sync(0xffffffffu, ss, o);
    if ((tid & 31) == 0) red[tid >> 5] = ss;
    __syncthreads();
    __shared__ float bscale;
    if (tid == 0) {
        float s = 0.f;
        #pragma unroll
        for (int i = 0; i < 8; i++) s += red[i];
        bscale = 32.0f * rsqrtf(s);
    }
    __syncthreads();
    float sc = bscale;
    float4 g = ((const float4*)gamma)[tid];
    float4 o;
    o.x = v.x * sc * g.x; o.y = v.y * sc * g.y;
    o.z = v.z * sc * g.z; o.w = v.w * sc * g.w;
    ((float4*)(g_xn + (size_t)t * DIM))[tid] = o;
}

// ---------------- gates -------------------------------------------------------
__global__ __launch_bounds__(512) void gates_kernel(const float* __restrict__ wg,
                                                    const float* __restrict__ bg) {
    int t = blockIdx.x;
    int h = threadIdx.x >> 5;
    int lane = threadIdx.x & 31;
    const float* xr = g_xn + (size_t)t * DIM;
    float s = 0.f;
    #pragma unroll 8
    for (int k = lane; k < DIM; k += 32)
        s += xr[k] * wg[k * HEADS + h];
    #pragma unroll
    for (int o = 16; o; o >>= 1) s += __shfl_down_sync(0xffffffffu, s, o);
    if (lane == 0) {
        float z = s + bg[h];
        g_gates[t * HEADS + h] = 1.f / (1.f + __expf(-z));
    }
}

// ---------------- tiled SGEMM with packed f32x2 inner product ------------------
// 128x128x8 tiles, 256 threads, 8x8 per thread as 8 rows x 4 f32x2 pairs.
// MODE 0: A=g_xn, B=w_qkv [1024x3072]; epilogue RoPE + scatter q/k/v.
// MODE 1: A=g_merged, B=w_out [1024x1024]; plain store.
template<int MODE>
__global__ __launch_bounds__(256) void sgemm_kernel(const float* __restrict__ B,
                                                    float* __restrict__ C) {
    const int N = (MODE == 0) ? QKV_N : DIM;
    const int K = DIM;
    const float* A = (MODE == 0) ? g_xn : g_merged;

    __shared__ float As[8][128];
    __shared__ float Bs[8][128];
    int tid = threadIdx.x;
    int a_row = tid >> 1, a_col = (tid & 1) * 4;
    int b_row = tid >> 5, b_col = (tid & 31) * 4;
    int tx = tid & 15, ty = tid >> 4;

    const float* Ab = A + (size_t)(blockIdx.y * 128) * K;
    const float* Bb = B + blockIdx.x * 128;

    u64 acc2[8][4];
    #pragma unroll
    for (int i = 0; i < 8; i++)
        #pragma unroll
        for (int j = 0; j < 4; j++) acc2[i][j] = 0ull;

    for (int k0 = 0; k0 < K; k0 += 8) {
        float4 av = *(const float4*)(Ab + (size_t)a_row * K + k0 + a_col);
        As[a_col + 0][a_row] = av.x;
        As[a_col + 1][a_row] = av.y;
        As[a_col + 2][a_row] = av.z;
        As[a_col + 3][a_row] = av.w;
        *(float4*)&Bs[b_row][b_col] = *(const float4*)(Bb + (size_t)(k0 + b_row) * N + b_col);
        __syncthreads();
        #pragma unroll
        for (int kk = 0; kk < 8; kk++) {
            float4 a0 = *(const float4*)&As[kk][ty * 4];
            float4 a1 = *(const float4*)&As[kk][64 + ty * 4];
            ulonglong2 bp0 = *(const ulonglong2*)&Bs[kk][tx * 4];
            ulonglong2 bp1 = *(const ulonglong2*)&Bs[kk][64 + tx * 4];
            u64 bp[4] = {bp0.x, bp0.y, bp1.x, bp1.y};
            float ar[8] = {a0.x, a0.y, a0.z, a0.w, a1.x, a1.y, a1.z, a1.w};
            #pragma unroll
            for (int i = 0; i < 8; i++) {
                u64 ap = pack2(ar[i]);
                #pragma unroll
                for (int j = 0; j < 4; j++)
                    FMA2(acc2[i][j], ap, bp[j]);
            }
        }
        __syncthreads();
    }

    #pragma unroll
    for (int ri = 0; ri < 2; ri++) {
        #pragma unroll
        for (int i = 0; i < 4; i++) {
            int r = ri * 64 + ty * 4 + i;
            int t = blockIdx.y * 128 + r;
            #pragma unroll
            for (int rj = 0; rj < 2; rj++) {
                int c = blockIdx.x * 128 + rj * 64 + tx * 4;
                float v0, v1, v2, v3;
                unpack2(acc2[ri*4+i][rj*2+0], v0, v1);
                unpack2(acc2[ri*4+i][rj*2+1], v2, v3);
                if (MODE == 1) {
                    *(float4*)(C + (size_t)t * N + c) = make_float4(v0, v1, v2, v3);
                } else {
                    int b = t >> 11, pos = t & (SEQ - 1);
                    int s = c >> 10;
                    int rem = c & 1023;
                    int h = rem >> 6;
                    int dd = rem & 63;
                    float4 o;
                    if (s < 2) {
                        const float* rp = g_rope + pos * 64 + dd;   // dd multiple of 4, pairs aligned
                        float c0 = rp[0], s0 = rp[1], c1 = rp[2], s1 = rp[3];
                        o.x = v0 * c0 - v1 * s0;
                        o.y = v1 * c0 + v0 * s0;
                        o.z = v2 * c1 - v3 * s1;
                        o.w = v3 * c1 + v2 * s1;
                    } else {
                        o = make_float4(v0, v1, v2, v3);
                    }
                    float* dst = (s == 0) ? g_q : ((s == 1) ? g_k : g_v);
                    *(float4*)(dst + ((size_t)(b * HEADS + h) * SEQ + pos) * DHEAD + dd) = o;
                }
            }
        }
    }
}

// ---------------- flash attention, packed f32x2, staged softmax ---------------
// grid (SEQ/128, 32), 128 threads; one q row per thread; 32-key tiles.
__global__ __launch_bounds__(128) void attn_kernel() {
    __shared__ float4 Ks[32 * 16];
    __shared__ float4 Vs[32 * 16];
    __shared__ float  Ss[32 * 128];
    int bh = blockIdx.y;
    int b = bh >> 4, h = bh & 15;
    int qrow = blockIdx.x * 128 + threadIdx.x;
    int tid = threadIdx.x;

    const ulonglong2* qp = (const ulonglong2*)(g_q + ((size_t)bh * SEQ + qrow) * DHEAD);
    u64 q2[32];
    #pragma unroll
    for (int i = 0; i < 16; i++) {
        ulonglong2 u = qp[i];
        q2[2*i] = u.x; q2[2*i+1] = u.y;
    }

    u64 acc2[32];
    #pragma unroll
    for (int i = 0; i < 32; i++) acc2[i] = 0ull;
    float m = -1e30f, l = 0.f;

    for (int kt = 0; kt < SEQ; kt += 32) {
        const float4* kb = (const float4*)(g_k + ((size_t)bh * SEQ + kt) * DHEAD);
        const float4* vb = (const float4*)(g_v + ((size_t)bh * SEQ + kt) * DHEAD);
        #pragma unroll
        for (int i = 0; i < 4; i++) {
            Ks[tid + i * 128] = kb[tid + i * 128];
            Vs[tid + i * 128] = vb[tid + i * 128];
        }
        __syncthreads();

        // pass 1: scores -> smem (packed dot), tile max
        float tmax = -1e30f;
        #pragma unroll 2
        for (int j = 0; j < 32; j++) {
            const u64* kr = (const u64*)&Ks[j * 16];
            u64 d0 = 0ull, d1 = 0ull, d2 = 0ull, d3 = 0ull;
            #pragma unroll
            for (int d = 0; d < 8; d++) {
                FMA2(d0, q2[4*d+0], kr[4*d+0]);
                FMA2(d1, q2[4*d+1], kr[4*d+1]);
                FMA2(d2, q2[4*d+2], kr[4*d+2]);
                FMA2(d3, q2[4*d+3], kr[4*d+3]);
            }
            float x0, x1, x2, x3, x4, x5, x6, x7;
            unpack2(d0, x0, x1); unpack2(d1, x2, x3);
            unpack2(d2, x4, x5); unpack2(d3, x6, x7);
            float s = ((x0 + x2) + (x1 + x3)) + ((x4 + x6) + (x5 + x7));
            s *= 0.125f;
            Ss[j * 128 + tid] = s;
            tmax = fmaxf(tmax, s);
        }

        // single rescale per tile
        float mn = fmaxf(m, tmax);
        float corr = __expf(m - mn);
        m = mn;
        l *= corr;
        u64 c2 = pack2(corr);
        #pragma unroll
        for (int d = 0; d < 32; d++) MUL2(acc2[d], acc2[d], c2);

        // pass 2: exp + packed accumulate
        #pragma unroll 2
        for (int j = 0; j < 32; j++) {
            float p = __expf(Ss[j * 128 + tid] - m);
            l += p;
            u64 p2 = pack2(p);
            const u64* vr = (const u64*)&Vs[j * 16];
            #pragma unroll
            for (int d = 0; d < 32; d++)
                FMA2(acc2[d], p2, vr[d]);
        }
        __syncthreads();
    }

    int t = b * SEQ + qrow;
    float gate = g_gates[t * HEADS + h];
    float inv = gate / l;
    float* op = g_merged + (size_t)t * DIM + h * DHEAD;
    #pragma unroll
    for (int d = 0; d < 32; d++) {
        float lo, hi;
        unpack2(acc2[d], lo, hi);
        float2 o; o.x = lo * inv; o.y = hi * inv;
        *(float2*)(op + 2*d) = o;
    }
}

// ---------------- launch ------------------------------------------------------
extern "C" void kernel_launch(void* const* d_in, const int* in_sizes, int n_in,
                              void* d_out, int out_size) {
    const float* x       = (const float*)d_in[0];
    const float* gamma   = (const float*)d_in[1];
    const float* w_qkv   = (const float*)d_in[2];
    const float* w_gates = (const float*)d_in[3];
    const float* b_gates = (const float*)d_in[4];
    const float* w_out   = (const float*)d_in[5];
    const float* freqs   = (const float*)d_in[6];
    float* out = (float*)d_out;

    rope_table_kernel<<<(SEQ * 32 + 255) / 256, 256>>>(freqs);
    rmsnorm_kernel<<<TOKENS, 256>>>(x, gamma);
    gates_kernel<<<TOKENS, 512>>>(w_gates, b_gates);
    {
        dim3 grid(QKV_N / 128, TOKENS / 128);
        sgemm_kernel<0><<<grid, 256>>>(w_qkv, nullptr);
    }
    {
        dim3 grid(SEQ / 128, BATCH * HEADS);
        attn_kernel<<<grid, 128>>>();
    }
    {
        dim3 grid(DIM / 128, TOKENS / 128);
        sgemm_kernel<1><<<grid, 256>>>(w_out, out);
    }
}